// round 2
// baseline (speedup 1.0000x reference)
#include <cuda_runtime.h>
#include <math.h>

// Problem constants
#define BATCH 2
#define SEQ   2048
#define DMOD  1024
#define NH    16
#define DK    64
#define MROWS (BATCH*SEQ)   // 4096

// Scratch (allocation-free per harness rules)
__device__ float g_Q[BATCH*NH*SEQ*DK];   // [b][h][s][dk], post-RoPE
__device__ float g_K[BATCH*NH*SEQ*DK];   // [b][h][s][dk], post-RoPE
__device__ float g_V[BATCH*NH*SEQ*DK];   // [b][h][s][dk]
__device__ float g_O[MROWS*DMOD];        // [b][s][h*dk]  (attention output)

// ---------------------------------------------------------------------------
// Tiled fp32 GEMM:  C[m][n] = sum_k A[m][k] * W[n][k]   (i.e. A @ W^T)
// M=4096, N=1024, K=1024.  128x128 tile, BK=16, 256 threads, 8x8 micro-tile.
// mode 0: Q proj + RoPE -> g_Q      mode 1: K proj + RoPE -> g_K
// mode 2: V proj        -> g_V      mode 3: A=g_O, plain   -> out (d_out)
// ---------------------------------------------------------------------------
#define BM 128
#define BN 128
#define BK 16

__global__ __launch_bounds__(256) void gemm_rope_kernel(
    const float* __restrict__ Ain, const float* __restrict__ W,
    float* __restrict__ out, int mode)
{
    const float* A = (mode == 3) ? g_O : Ain;

    __shared__ float As[BK][BM + 4];
    __shared__ float Bs[BK][BN + 4];

    const int tx = threadIdx.x & 15;     // 0..15  -> n
    const int ty = threadIdx.x >> 4;     // 0..15  -> m
    const int m0 = blockIdx.y * BM;
    const int n0 = blockIdx.x * BN;

    float acc[8][8];
#pragma unroll
    for (int i = 0; i < 8; i++)
#pragma unroll
        for (int j = 0; j < 8; j++) acc[i][j] = 0.f;

    for (int k0 = 0; k0 < DMOD; k0 += BK) {
        // Load A tile: 128 rows x 16 k = 512 float4, 2 per thread
#pragma unroll
        for (int i = 0; i < 2; i++) {
            int idx = threadIdx.x * 2 + i;          // 0..511
            int row = idx >> 2;                     // 0..127
            int kk  = (idx & 3) * 4;                // 0,4,8,12
            float4 v = *(const float4*)&A[(size_t)(m0 + row) * DMOD + k0 + kk];
            As[kk + 0][row] = v.x; As[kk + 1][row] = v.y;
            As[kk + 2][row] = v.z; As[kk + 3][row] = v.w;
        }
        // Load W tile (as B^T): Bs[k][n] = W[n0+n][k0+k]
#pragma unroll
        for (int i = 0; i < 2; i++) {
            int idx = threadIdx.x * 2 + i;
            int col = idx >> 2;
            int kk  = (idx & 3) * 4;
            float4 v = *(const float4*)&W[(size_t)(n0 + col) * DMOD + k0 + kk];
            Bs[kk + 0][col] = v.x; Bs[kk + 1][col] = v.y;
            Bs[kk + 2][col] = v.z; Bs[kk + 3][col] = v.w;
        }
        __syncthreads();

#pragma unroll
        for (int k = 0; k < BK; k++) {
            float a[8], b[8];
#pragma unroll
            for (int i = 0; i < 4; i++) {
                a[i]     = As[k][ty * 4 + i];
                a[4 + i] = As[k][64 + ty * 4 + i];
                b[i]     = Bs[k][tx * 4 + i];
                b[4 + i] = Bs[k][64 + tx * 4 + i];
            }
#pragma unroll
            for (int i = 0; i < 8; i++)
#pragma unroll
                for (int j = 0; j < 8; j++)
                    acc[i][j] += a[i] * b[j];
        }
        __syncthreads();
    }

    // Epilogue
#pragma unroll
    for (int ri = 0; ri < 8; ri++) {
        int r = ((ri & 4) ? 64 : 0) + ty * 4 + (ri & 3);
        int m = m0 + r;
        int bb = m >> 11;            // m / SEQ
        int ss = m & (SEQ - 1);
#pragma unroll
        for (int g = 0; g < 2; g++) {
            int nbase = n0 + g * 64 + tx * 4;     // 4 consecutive cols, even-aligned
            if (mode == 3) {
#pragma unroll
                for (int j = 0; j < 4; j++)
                    out[(size_t)m * DMOD + nbase + j] = acc[ri][g * 4 + j];
            } else if (mode == 2) {
                int h  = nbase >> 6;
                int i0 = nbase & 63;
                float* dst = &g_V[(((size_t)(bb * NH + h)) * SEQ + ss) * DK + i0];
#pragma unroll
                for (int j = 0; j < 4; j++) dst[j] = acc[ri][g * 4 + j];
            } else {
                int h  = nbase >> 6;
                int i0 = nbase & 63;
                float* dst = ((mode == 0) ? g_Q : g_K)
                           + (((size_t)(bb * NH + h)) * SEQ + ss) * DK + i0;
#pragma unroll
                for (int p = 0; p < 2; p++) {
                    int i = i0 + 2 * p;                       // even index = 2j
                    float invf = powf(10000.0f, -(float)i / 64.0f);  // theta^(-2j/dk)
                    float ang  = (float)ss * invf;
                    float sn, cs;
                    sincosf(ang, &sn, &cs);
                    float x0 = acc[ri][g * 4 + 2 * p];
                    float x1 = acc[ri][g * 4 + 2 * p + 1];
                    dst[2 * p]     = x0 * cs - x1 * sn;
                    dst[2 * p + 1] = x1 * cs + x0 * sn;
                }
            }
        }
    }
}

// ---------------------------------------------------------------------------
// Causal flash attention, fp32.  1 thread = 1 query row (q,o in registers),
// 64-key tiles staged in smem, chunked-16 online softmax.
// grid = (SEQ/128, BATCH*NH), block = 128
// ---------------------------------------------------------------------------
__global__ __launch_bounds__(128) void attn_kernel()
{
    const int tid = threadIdx.x;
    const int qt  = blockIdx.x;
    const int bh  = blockIdx.y;
    const int qi  = qt * 128 + tid;

    const float* Qb = g_Q + (size_t)bh * SEQ * DK;
    const float* Kb = g_K + (size_t)bh * SEQ * DK;
    const float* Vb = g_V + (size_t)bh * SEQ * DK;

    __shared__ float Ks[64 * DK];
    __shared__ float Vs[64 * DK];

    float4 q4[16];
    {
        const float4* qp = (const float4*)(Qb + (size_t)qi * DK);
#pragma unroll
        for (int i = 0; i < 16; i++) q4[i] = qp[i];
    }

    float4 o4[16];
#pragma unroll
    for (int i = 0; i < 16; i++) o4[i] = make_float4(0.f, 0.f, 0.f, 0.f);
    float mrow = -INFINITY, l = 0.f;

    const int ktmax = 2 * qt + 1;
    for (int kt = 0; kt <= ktmax; kt++) {
        const float4* kg  = (const float4*)(Kb + (size_t)kt * 64 * DK);
        const float4* vg  = (const float4*)(Vb + (size_t)kt * 64 * DK);
        float4* ks4 = (float4*)Ks;
        float4* vs4 = (float4*)Vs;
        __syncthreads();
#pragma unroll
        for (int i = 0; i < 8; i++) {
            ks4[tid + i * 128] = kg[tid + i * 128];
            vs4[tid + i * 128] = vg[tid + i * 128];
        }
        __syncthreads();

#pragma unroll 1
        for (int c = 0; c < 4; c++) {
            float p[16];
            float cm = -INFINITY;
#pragma unroll
            for (int jj = 0; jj < 16; jj++) {
                int j  = c * 16 + jj;
                int kj = kt * 64 + j;
                float s = -INFINITY;
                if (kj <= qi) {
                    const float4* kp = (const float4*)(Ks + j * DK);
                    float ax = 0.f, ay = 0.f, az = 0.f, aw = 0.f;
#pragma unroll
                    for (int d = 0; d < 16; d++) {
                        float4 kv = kp[d];
                        ax += q4[d].x * kv.x;
                        ay += q4[d].y * kv.y;
                        az += q4[d].z * kv.z;
                        aw += q4[d].w * kv.w;
                    }
                    s = (ax + ay + az + aw) * 0.125f;   // 1/sqrt(64)
                }
                p[jj] = s;
                cm = fmaxf(cm, s);
            }
            if (cm == -INFINITY) continue;   // entire chunk masked

            float mnew = fmaxf(mrow, cm);
            float corr = __expf(mrow - mnew);   // 0 when mrow == -inf
            l *= corr;
#pragma unroll
            for (int i = 0; i < 16; i++) {
                o4[i].x *= corr; o4[i].y *= corr;
                o4[i].z *= corr; o4[i].w *= corr;
            }
#pragma unroll
            for (int jj = 0; jj < 16; jj++) {
                float pv = __expf(p[jj] - mnew);    // 0 for masked entries
                if (pv > 0.f) {
                    l += pv;
                    const float4* vp = (const float4*)(Vs + (c * 16 + jj) * DK);
#pragma unroll
                    for (int d = 0; d < 16; d++) {
                        float4 vv = vp[d];
                        o4[d].x += pv * vv.x;
                        o4[d].y += pv * vv.y;
                        o4[d].z += pv * vv.z;
                        o4[d].w += pv * vv.w;
                    }
                }
            }
            mrow = mnew;
        }
    }

    // Write O[b][s][h*dk + d]
    const int bb = bh >> 4;
    const int h  = bh & 15;
    const float inv = 1.f / l;
    float4* dst = (float4*)(g_O + ((size_t)(bb * SEQ + qi)) * DMOD + h * DK);
#pragma unroll
    for (int i = 0; i < 16; i++) {
        float4 v = o4[i];
        v.x *= inv; v.y *= inv; v.z *= inv; v.w *= inv;
        dst[i] = v;
    }
}

// ---------------------------------------------------------------------------
extern "C" void kernel_launch(void* const* d_in, const int* in_sizes, int n_in,
                              void* d_out, int out_size)
{
    const float* X  = (const float*)d_in[0];
    const float* Wq = (const float*)d_in[1];
    const float* Wk = (const float*)d_in[2];
    const float* Wv = (const float*)d_in[3];
    const float* Wo = (const float*)d_in[4];
    float* out = (float*)d_out;

    dim3 ggrid(DMOD / BN, MROWS / BM);   // (8, 32)
    dim3 gblk(256);

    gemm_rope_kernel<<<ggrid, gblk>>>(X, Wq, nullptr, 0);
    gemm_rope_kernel<<<ggrid, gblk>>>(X, Wk, nullptr, 1);
    gemm_rope_kernel<<<ggrid, gblk>>>(X, Wv, nullptr, 2);

    dim3 agrid(SEQ / 128, BATCH * NH);   // (16, 32)
    attn_kernel<<<agrid, 128>>>();

    gemm_rope_kernel<<<ggrid, gblk>>>(X /*ignored*/, Wo, out, 3);
}

// round 3
// speedup vs baseline: 1.2192x; 1.2192x over previous
#include <cuda_runtime.h>
#include <cuda_bf16.h>
#include <math.h>
#include <stdint.h>

// Problem constants
#define BATCH 2
#define SEQ   2048
#define DMOD  1024
#define NH    16
#define DK    64
#define MROWS (BATCH*SEQ)   // 4096

// Scratch (allocation-free per harness rules)
__device__ float g_Q[BATCH*NH*SEQ*DK];   // [b][h][s][dk], post-RoPE
__device__ float g_K[BATCH*NH*SEQ*DK];   // [b][h][s][dk], post-RoPE
__device__ float g_V[BATCH*NH*SEQ*DK];   // [b][h][s][dk]
__device__ float g_O[MROWS*DMOD];        // [b][s][h*dk]  (attention output)

// ---------------------------------------------------------------------------
// bf16 split helpers: x = hi + lo, each bf16 -> ~16 mantissa bits recovered
// ---------------------------------------------------------------------------
__device__ __forceinline__ void split2(float e, float o, uint32_t& hi, uint32_t& lo)
{
    __nv_bfloat16 eh = __float2bfloat16(e);
    __nv_bfloat16 oh = __float2bfloat16(o);
    float er = e - __bfloat162float(eh);
    float orr = o - __bfloat162float(oh);
    __nv_bfloat16 el = __float2bfloat16(er);
    __nv_bfloat16 ol = __float2bfloat16(orr);
    hi = (uint32_t)__bfloat16_as_ushort(eh) | ((uint32_t)__bfloat16_as_ushort(oh) << 16);
    lo = (uint32_t)__bfloat16_as_ushort(el) | ((uint32_t)__bfloat16_as_ushort(ol) << 16);
}

__device__ __forceinline__ void mma16816(float* c, const uint32_t* a, const uint32_t* b)
{
    asm volatile(
        "mma.sync.aligned.m16n8k16.row.col.f32.bf16.bf16.f32 "
        "{%0,%1,%2,%3}, {%4,%5,%6,%7}, {%8,%9}, {%0,%1,%2,%3};\n"
        : "+f"(c[0]), "+f"(c[1]), "+f"(c[2]), "+f"(c[3])
        : "r"(a[0]), "r"(a[1]), "r"(a[2]), "r"(a[3]), "r"(b[0]), "r"(b[1]));
}

// ---------------------------------------------------------------------------
// Tensor-core GEMM (3xBF16 split): C[m][n] = sum_k A[m][k] * W[n][k]
// M=4096, N=1024, K=1024. Block tile 128x64, BK=32 fp32, 256 threads (8 warps,
// warp tile 32x32 = 2x4 m16n8k16 tiles). Fused epilogues:
//   mode 0: Q proj + RoPE -> g_Q    mode 1: K proj + RoPE -> g_K
//   mode 2: V proj        -> g_V    mode 3: A=g_O, plain  -> out
// ---------------------------------------------------------------------------
__global__ __launch_bounds__(256) void gemm_mma_kernel(
    const float* __restrict__ Ain, const float* __restrict__ W,
    float* __restrict__ out, int mode)
{
    const float* A = (mode == 3) ? g_O : Ain;

    // k-pair-major smem; row strides 136/72 (== 8 mod 32) => conflict-free frag LDS
    __shared__ uint32_t sAh[16][136];
    __shared__ uint32_t sAl[16][136];
    __shared__ uint32_t sBh[16][72];
    __shared__ uint32_t sBl[16][72];

    const int tid  = threadIdx.x;
    const int warp = tid >> 5, lane = tid & 31;
    const int g = lane >> 2, t = lane & 3;
    const int wr = warp >> 1;        // 0..3 -> m offset wr*32
    const int wc = warp & 1;         // 0..1 -> n offset wc*32
    const int m0 = blockIdx.y * 128;
    const int n0 = blockIdx.x * 64;

    float acc[2][4][4];
#pragma unroll
    for (int mt = 0; mt < 2; mt++)
#pragma unroll
        for (int nt = 0; nt < 4; nt++)
#pragma unroll
            for (int i = 0; i < 4; i++) acc[mt][nt][i] = 0.f;

    for (int k0 = 0; k0 < DMOD; k0 += 32) {
        // --- load + split A tile: 128 rows x 32 k = 1024 float4, 4/thread ---
#pragma unroll
        for (int i = 0; i < 4; i++) {
            int lin = tid + i * 256;
            int row = lin >> 3;                 // 0..127
            int kq  = (lin & 7) * 4;            // 0,4,...,28
            float4 v = *(const float4*)&A[(size_t)(m0 + row) * DMOD + k0 + kq];
            uint32_t h0, l0, h1, l1;
            split2(v.x, v.y, h0, l0);
            split2(v.z, v.w, h1, l1);
            int kp = kq >> 1;
            sAh[kp][row] = h0; sAl[kp][row] = l0;
            sAh[kp + 1][row] = h1; sAl[kp + 1][row] = l1;
        }
        // --- load + split B tile: 64 rows x 32 k = 512 float4, 2/thread ---
#pragma unroll
        for (int i = 0; i < 2; i++) {
            int lin = tid + i * 256;
            int row = lin >> 3;                 // 0..63
            int kq  = (lin & 7) * 4;
            float4 v = *(const float4*)&W[(size_t)(n0 + row) * DMOD + k0 + kq];
            uint32_t h0, l0, h1, l1;
            split2(v.x, v.y, h0, l0);
            split2(v.z, v.w, h1, l1);
            int kp = kq >> 1;
            sBh[kp][row] = h0; sBl[kp][row] = l0;
            sBh[kp + 1][row] = h1; sBl[kp + 1][row] = l1;
        }
        __syncthreads();

#pragma unroll
        for (int s = 0; s < 2; s++) {           // two k16 steps per BK=32
            const int kr = s * 8 + t;
            uint32_t ah[2][4], al[2][4], bh[4][2], bl[4][2];
#pragma unroll
            for (int mt = 0; mt < 2; mt++) {
                int mc = wr * 32 + mt * 16 + g;
                ah[mt][0] = sAh[kr][mc];     ah[mt][1] = sAh[kr][mc + 8];
                ah[mt][2] = sAh[kr + 4][mc]; ah[mt][3] = sAh[kr + 4][mc + 8];
                al[mt][0] = sAl[kr][mc];     al[mt][1] = sAl[kr][mc + 8];
                al[mt][2] = sAl[kr + 4][mc]; al[mt][3] = sAl[kr + 4][mc + 8];
            }
#pragma unroll
            for (int nt = 0; nt < 4; nt++) {
                int nc = wc * 32 + nt * 8 + g;
                bh[nt][0] = sBh[kr][nc]; bh[nt][1] = sBh[kr + 4][nc];
                bl[nt][0] = sBl[kr][nc]; bl[nt][1] = sBl[kr + 4][nc];
            }
#pragma unroll
            for (int mt = 0; mt < 2; mt++)
#pragma unroll
                for (int nt = 0; nt < 4; nt++) {
                    mma16816(acc[mt][nt], al[mt], bh[nt]);  // small terms first
                    mma16816(acc[mt][nt], ah[mt], bl[nt]);
                    mma16816(acc[mt][nt], ah[mt], bh[nt]);
                }
        }
        __syncthreads();
    }

    // --- epilogue: each thread owns pairs (col 2t, 2t+1) at rows g / g+8 ---
#pragma unroll
    for (int mt = 0; mt < 2; mt++) {
#pragma unroll
        for (int rh = 0; rh < 2; rh++) {
            int m  = m0 + wr * 32 + mt * 16 + g + rh * 8;
            int bb = m >> 11;            // m / SEQ
            int ss = m & (SEQ - 1);
#pragma unroll
            for (int nt = 0; nt < 4; nt++) {
                float c0 = acc[mt][nt][rh * 2 + 0];
                float c1 = acc[mt][nt][rh * 2 + 1];
                int n = n0 + wc * 32 + nt * 8 + t * 2;      // even
                if (mode == 3) {
                    *(float2*)&out[(size_t)m * DMOD + n] = make_float2(c0, c1);
                } else if (mode == 2) {
                    int h = n >> 6, i0 = n & 63;
                    *(float2*)&g_V[(((size_t)(bb * NH + h)) * SEQ + ss) * DK + i0] =
                        make_float2(c0, c1);
                } else {
                    int h = n >> 6, i0 = n & 63;
                    float invf = powf(10000.0f, -(float)i0 / 64.0f);
                    float ang  = (float)ss * invf;
                    float sn, cs;
                    sincosf(ang, &sn, &cs);
                    float r0 = c0 * cs - c1 * sn;
                    float r1 = c1 * cs + c0 * sn;
                    float* dst = ((mode == 0) ? g_Q : g_K)
                               + (((size_t)(bb * NH + h)) * SEQ + ss) * DK + i0;
                    *(float2*)dst = make_float2(r0, r1);
                }
            }
        }
    }
}

// ---------------------------------------------------------------------------
// Causal flash attention, fp32 (unchanged from R1; R3 target).
// ---------------------------------------------------------------------------
__global__ __launch_bounds__(128) void attn_kernel()
{
    const int tid = threadIdx.x;
    const int qt  = blockIdx.x;
    const int bh  = blockIdx.y;
    const int qi  = qt * 128 + tid;

    const float* Qb = g_Q + (size_t)bh * SEQ * DK;
    const float* Kb = g_K + (size_t)bh * SEQ * DK;
    const float* Vb = g_V + (size_t)bh * SEQ * DK;

    __shared__ float Ks[64 * DK];
    __shared__ float Vs[64 * DK];

    float4 q4[16];
    {
        const float4* qp = (const float4*)(Qb + (size_t)qi * DK);
#pragma unroll
        for (int i = 0; i < 16; i++) q4[i] = qp[i];
    }

    float4 o4[16];
#pragma unroll
    for (int i = 0; i < 16; i++) o4[i] = make_float4(0.f, 0.f, 0.f, 0.f);
    float mrow = -INFINITY, l = 0.f;

    const int ktmax = 2 * qt + 1;
    for (int kt = 0; kt <= ktmax; kt++) {
        const float4* kg = (const float4*)(Kb + (size_t)kt * 64 * DK);
        const float4* vg = (const float4*)(Vb + (size_t)kt * 64 * DK);
        float4* ks4 = (float4*)Ks;
        float4* vs4 = (float4*)Vs;
        __syncthreads();
#pragma unroll
        for (int i = 0; i < 8; i++) {
            ks4[tid + i * 128] = kg[tid + i * 128];
            vs4[tid + i * 128] = vg[tid + i * 128];
        }
        __syncthreads();

#pragma unroll 1
        for (int c = 0; c < 4; c++) {
            float p[16];
            float cm = -INFINITY;
#pragma unroll
            for (int jj = 0; jj < 16; jj++) {
                int j  = c * 16 + jj;
                int kj = kt * 64 + j;
                float s = -INFINITY;
                if (kj <= qi) {
                    const float4* kp = (const float4*)(Ks + j * DK);
                    float ax = 0.f, ay = 0.f, az = 0.f, aw = 0.f;
#pragma unroll
                    for (int d = 0; d < 16; d++) {
                        float4 kv = kp[d];
                        ax += q4[d].x * kv.x;
                        ay += q4[d].y * kv.y;
                        az += q4[d].z * kv.z;
                        aw += q4[d].w * kv.w;
                    }
                    s = (ax + ay + az + aw) * 0.125f;   // 1/sqrt(64)
                }
                p[jj] = s;
                cm = fmaxf(cm, s);
            }
            if (cm == -INFINITY) continue;

            float mnew = fmaxf(mrow, cm);
            float corr = __expf(mrow - mnew);
            l *= corr;
#pragma unroll
            for (int i = 0; i < 16; i++) {
                o4[i].x *= corr; o4[i].y *= corr;
                o4[i].z *= corr; o4[i].w *= corr;
            }
#pragma unroll
            for (int jj = 0; jj < 16; jj++) {
                float pv = __expf(p[jj] - mnew);
                if (pv > 0.f) {
                    l += pv;
                    const float4* vp = (const float4*)(Vs + (c * 16 + jj) * DK);
#pragma unroll
                    for (int d = 0; d < 16; d++) {
                        float4 vv = vp[d];
                        o4[d].x += pv * vv.x;
                        o4[d].y += pv * vv.y;
                        o4[d].z += pv * vv.z;
                        o4[d].w += pv * vv.w;
                    }
                }
            }
            mrow = mnew;
        }
    }

    const int bb = bh >> 4;
    const int h  = bh & 15;
    const float inv = 1.f / l;
    float4* dst = (float4*)(g_O + ((size_t)(bb * SEQ + qi)) * DMOD + h * DK);
#pragma unroll
    for (int i = 0; i < 16; i++) {
        float4 v = o4[i];
        v.x *= inv; v.y *= inv; v.z *= inv; v.w *= inv;
        dst[i] = v;
    }
}

// ---------------------------------------------------------------------------
extern "C" void kernel_launch(void* const* d_in, const int* in_sizes, int n_in,
                              void* d_out, int out_size)
{
    const float* X  = (const float*)d_in[0];
    const float* Wq = (const float*)d_in[1];
    const float* Wk = (const float*)d_in[2];
    const float* Wv = (const float*)d_in[3];
    const float* Wo = (const float*)d_in[4];
    float* out = (float*)d_out;

    dim3 ggrid(DMOD / 64, MROWS / 128);   // (16, 32)
    dim3 gblk(256);

    gemm_mma_kernel<<<ggrid, gblk>>>(X, Wq, nullptr, 0);
    gemm_mma_kernel<<<ggrid, gblk>>>(X, Wk, nullptr, 1);
    gemm_mma_kernel<<<ggrid, gblk>>>(X, Wv, nullptr, 2);

    dim3 agrid(SEQ / 128, BATCH * NH);    // (16, 32)
    attn_kernel<<<agrid, 128>>>();

    gemm_mma_kernel<<<ggrid, gblk>>>(X /*ignored*/, Wo, out, 3);
}

// round 4
// speedup vs baseline: 2.5711x; 2.1089x over previous
#include <cuda_runtime.h>
#include <cuda_bf16.h>
#include <math.h>
#include <stdint.h>

// Problem constants
#define BATCH 2
#define SEQ   2048
#define DMOD  1024
#define NH    16
#define DK    64
#define MROWS (BATCH*SEQ)   // 4096

// Scratch (allocation-free per harness rules)
__device__ float g_Q[BATCH*NH*SEQ*DK];   // [b][h][s][dk], post-RoPE
__device__ float g_K[BATCH*NH*SEQ*DK];   // [b][h][s][dk], post-RoPE
__device__ float g_V[BATCH*NH*SEQ*DK];   // [b][h][s][dk]
__device__ float g_O[MROWS*DMOD];        // [b][s][h*dk]

// ---------------------------------------------------------------------------
// helpers
// ---------------------------------------------------------------------------
__device__ __forceinline__ void split2(float e, float o, uint32_t& hi, uint32_t& lo)
{
    __nv_bfloat16 eh = __float2bfloat16(e);
    __nv_bfloat16 oh = __float2bfloat16(o);
    float er  = e - __bfloat162float(eh);
    float orr = o - __bfloat162float(oh);
    __nv_bfloat16 el = __float2bfloat16(er);
    __nv_bfloat16 ol = __float2bfloat16(orr);
    hi = (uint32_t)__bfloat16_as_ushort(eh) | ((uint32_t)__bfloat16_as_ushort(oh) << 16);
    lo = (uint32_t)__bfloat16_as_ushort(el) | ((uint32_t)__bfloat16_as_ushort(ol) << 16);
}

__device__ __forceinline__ void mma16816(float* c, const uint32_t* a, const uint32_t* b)
{
    asm volatile(
        "mma.sync.aligned.m16n8k16.row.col.f32.bf16.bf16.f32 "
        "{%0,%1,%2,%3}, {%4,%5,%6,%7}, {%8,%9}, {%0,%1,%2,%3};\n"
        : "+f"(c[0]), "+f"(c[1]), "+f"(c[2]), "+f"(c[3])
        : "r"(a[0]), "r"(a[1]), "r"(a[2]), "r"(a[3]), "r"(b[0]), "r"(b[1]));
}

__device__ __forceinline__ void ldsm_x2(uint32_t& r0, uint32_t& r1, uint32_t addr)
{
    asm volatile("ldmatrix.sync.aligned.m8n8.x2.shared.b16 {%0,%1}, [%2];"
                 : "=r"(r0), "=r"(r1) : "r"(addr));
}
__device__ __forceinline__ void ldsm_x2_t(uint32_t& r0, uint32_t& r1, uint32_t addr)
{
    asm volatile("ldmatrix.sync.aligned.m8n8.x2.trans.shared.b16 {%0,%1}, [%2];"
                 : "=r"(r0), "=r"(r1) : "r"(addr));
}

// ---------------------------------------------------------------------------
// Tensor-core GEMM (3xBF16 split): C = A @ W^T  (unchanged from R2)
// ---------------------------------------------------------------------------
__global__ __launch_bounds__(256) void gemm_mma_kernel(
    const float* __restrict__ Ain, const float* __restrict__ W,
    float* __restrict__ out, int mode)
{
    const float* A = (mode == 3) ? g_O : Ain;

    __shared__ uint32_t sAh[16][136];
    __shared__ uint32_t sAl[16][136];
    __shared__ uint32_t sBh[16][72];
    __shared__ uint32_t sBl[16][72];

    const int tid  = threadIdx.x;
    const int warp = tid >> 5, lane = tid & 31;
    const int g = lane >> 2, t = lane & 3;
    const int wr = warp >> 1;
    const int wc = warp & 1;
    const int m0 = blockIdx.y * 128;
    const int n0 = blockIdx.x * 64;

    float acc[2][4][4];
#pragma unroll
    for (int mt = 0; mt < 2; mt++)
#pragma unroll
        for (int nt = 0; nt < 4; nt++)
#pragma unroll
            for (int i = 0; i < 4; i++) acc[mt][nt][i] = 0.f;

    for (int k0 = 0; k0 < DMOD; k0 += 32) {
#pragma unroll
        for (int i = 0; i < 4; i++) {
            int lin = tid + i * 256;
            int row = lin >> 3;
            int kq  = (lin & 7) * 4;
            float4 v = *(const float4*)&A[(size_t)(m0 + row) * DMOD + k0 + kq];
            uint32_t h0, l0, h1, l1;
            split2(v.x, v.y, h0, l0);
            split2(v.z, v.w, h1, l1);
            int kp = kq >> 1;
            sAh[kp][row] = h0; sAl[kp][row] = l0;
            sAh[kp + 1][row] = h1; sAl[kp + 1][row] = l1;
        }
#pragma unroll
        for (int i = 0; i < 2; i++) {
            int lin = tid + i * 256;
            int row = lin >> 3;
            int kq  = (lin & 7) * 4;
            float4 v = *(const float4*)&W[(size_t)(n0 + row) * DMOD + k0 + kq];
            uint32_t h0, l0, h1, l1;
            split2(v.x, v.y, h0, l0);
            split2(v.z, v.w, h1, l1);
            int kp = kq >> 1;
            sBh[kp][row] = h0; sBl[kp][row] = l0;
            sBh[kp + 1][row] = h1; sBl[kp + 1][row] = l1;
        }
        __syncthreads();

#pragma unroll
        for (int s = 0; s < 2; s++) {
            const int kr = s * 8 + t;
            uint32_t ah[2][4], al[2][4], bh[4][2], bl[4][2];
#pragma unroll
            for (int mt = 0; mt < 2; mt++) {
                int mc = wr * 32 + mt * 16 + g;
                ah[mt][0] = sAh[kr][mc];     ah[mt][1] = sAh[kr][mc + 8];
                ah[mt][2] = sAh[kr + 4][mc]; ah[mt][3] = sAh[kr + 4][mc + 8];
                al[mt][0] = sAl[kr][mc];     al[mt][1] = sAl[kr][mc + 8];
                al[mt][2] = sAl[kr + 4][mc]; al[mt][3] = sAl[kr + 4][mc + 8];
            }
#pragma unroll
            for (int nt = 0; nt < 4; nt++) {
                int nc = wc * 32 + nt * 8 + g;
                bh[nt][0] = sBh[kr][nc]; bh[nt][1] = sBh[kr + 4][nc];
                bl[nt][0] = sBl[kr][nc]; bl[nt][1] = sBl[kr + 4][nc];
            }
#pragma unroll
            for (int mt = 0; mt < 2; mt++)
#pragma unroll
                for (int nt = 0; nt < 4; nt++) {
                    mma16816(acc[mt][nt], al[mt], bh[nt]);
                    mma16816(acc[mt][nt], ah[mt], bl[nt]);
                    mma16816(acc[mt][nt], ah[mt], bh[nt]);
                }
        }
        __syncthreads();
    }

#pragma unroll
    for (int mt = 0; mt < 2; mt++) {
#pragma unroll
        for (int rh = 0; rh < 2; rh++) {
            int m  = m0 + wr * 32 + mt * 16 + g + rh * 8;
            int bb = m >> 11;
            int ss = m & (SEQ - 1);
#pragma unroll
            for (int nt = 0; nt < 4; nt++) {
                float c0 = acc[mt][nt][rh * 2 + 0];
                float c1 = acc[mt][nt][rh * 2 + 1];
                int n = n0 + wc * 32 + nt * 8 + t * 2;
                if (mode == 3) {
                    *(float2*)&out[(size_t)m * DMOD + n] = make_float2(c0, c1);
                } else if (mode == 2) {
                    int h = n >> 6, i0 = n & 63;
                    *(float2*)&g_V[(((size_t)(bb * NH + h)) * SEQ + ss) * DK + i0] =
                        make_float2(c0, c1);
                } else {
                    int h = n >> 6, i0 = n & 63;
                    float invf = powf(10000.0f, -(float)i0 / 64.0f);
                    float ang  = (float)ss * invf;
                    float sn, cs;
                    sincosf(ang, &sn, &cs);
                    float r0 = c0 * cs - c1 * sn;
                    float r1 = c1 * cs + c0 * sn;
                    float* dst = ((mode == 0) ? g_Q : g_K)
                               + (((size_t)(bb * NH + h)) * SEQ + ss) * DK + i0;
                    *(float2*)dst = make_float2(r0, r1);
                }
            }
        }
    }
}

// ---------------------------------------------------------------------------
// MMA flash attention (3xBF16 split for QK^T and PV), causal.
// CTA: 64 queries, 4 warps (16 q-rows each), 64-key tiles in smem.
// grid = (SEQ/64, BATCH*NH), block = 128
// ---------------------------------------------------------------------------
#define VPITCH 72   // bf16 row pitch for K/V smem tiles (conflict-free ldmatrix)

__global__ __launch_bounds__(128) void attn_mma_kernel()
{
    __shared__ __nv_bfloat16 Ksh[64 * VPITCH];
    __shared__ __nv_bfloat16 Ksl[64 * VPITCH];
    __shared__ __nv_bfloat16 Vsh[64 * VPITCH];
    __shared__ __nv_bfloat16 Vsl[64 * VPITCH];

    const int tid  = threadIdx.x;
    const int w    = tid >> 5;
    const int lane = tid & 31;
    const int g = lane >> 2, t = lane & 3;
    const int qt = (int)gridDim.x - 1 - (int)blockIdx.x;   // heavy blocks first
    const int bh = blockIdx.y;
    const int q0 = qt * 64;

    const float* Qb = g_Q + (size_t)bh * SEQ * DK;
    const float* Kb = g_K + (size_t)bh * SEQ * DK;
    const float* Vb = g_V + (size_t)bh * SEQ * DK;

    // --- Q fragments (rows q0 + w*16 + g, g+8), split hi/lo ---
    uint32_t qh[4][4], ql[4][4];
    {
        const float* Qr0 = Qb + (size_t)(q0 + w * 16 + g) * DK;
        const float* Qr8 = Qr0 + 8 * DK;
#pragma unroll
        for (int ks = 0; ks < 4; ks++) {
            float2 x0 = *(const float2*)&Qr0[ks * 16 + 2 * t];
            float2 x1 = *(const float2*)&Qr8[ks * 16 + 2 * t];
            float2 x2 = *(const float2*)&Qr0[ks * 16 + 8 + 2 * t];
            float2 x3 = *(const float2*)&Qr8[ks * 16 + 8 + 2 * t];
            split2(x0.x, x0.y, qh[ks][0], ql[ks][0]);
            split2(x1.x, x1.y, qh[ks][1], ql[ks][1]);
            split2(x2.x, x2.y, qh[ks][2], ql[ks][2]);
            split2(x3.x, x3.y, qh[ks][3], ql[ks][3]);
        }
    }

    // ldmatrix base addresses (u32 shared space) + per-lane partial offsets
    const uint32_t khB = (uint32_t)__cvta_generic_to_shared(Ksh);
    const uint32_t klB = (uint32_t)__cvta_generic_to_shared(Ksl);
    const uint32_t vhB = (uint32_t)__cvta_generic_to_shared(Vsh);
    const uint32_t vlB = (uint32_t)__cvta_generic_to_shared(Vsl);
    // K (non-trans): row = nt*8 + (lane&7), col = ks*16 + 8*((lane>>3)&1)
    const uint32_t kPart = ((lane & 7) * VPITCH + 8 * ((lane >> 3) & 1)) * 2;
    // V (trans): row = kc*16 + (lane&7) + 8*((lane>>3)&1), col = nt*8
    const uint32_t vPart = (((lane & 7) + 8 * ((lane >> 3) & 1)) * VPITCH) * 2;

    float oacc[8][4];
#pragma unroll
    for (int nt = 0; nt < 8; nt++)
#pragma unroll
        for (int i = 0; i < 4; i++) oacc[nt][i] = 0.f;
    float mrow[2] = {-1e30f, -1e30f};
    float lrow[2] = {0.f, 0.f};

    for (int kt = 0; kt <= qt; kt++) {
        __syncthreads();
        // --- load K,V tiles (64x64 fp32 each) -> split bf16 hi/lo smem ---
#pragma unroll
        for (int i = 0; i < 8; i++) {
            int lin = i * 128 + tid;
            int row = lin >> 4;
            int c4  = (lin & 15) * 4;
            const float* src = Kb + (size_t)(kt * 64 + row) * DK + c4;
            float4 v = *(const float4*)src;
            uint32_t h0, l0, h1, l1;
            split2(v.x, v.y, h0, l0);
            split2(v.z, v.w, h1, l1);
            *(uint32_t*)&Ksh[row * VPITCH + c4]     = h0;
            *(uint32_t*)&Ksh[row * VPITCH + c4 + 2] = h1;
            *(uint32_t*)&Ksl[row * VPITCH + c4]     = l0;
            *(uint32_t*)&Ksl[row * VPITCH + c4 + 2] = l1;

            const float* sv = Vb + (size_t)(kt * 64 + row) * DK + c4;
            float4 vv = *(const float4*)sv;
            split2(vv.x, vv.y, h0, l0);
            split2(vv.z, vv.w, h1, l1);
            *(uint32_t*)&Vsh[row * VPITCH + c4]     = h0;
            *(uint32_t*)&Vsh[row * VPITCH + c4 + 2] = h1;
            *(uint32_t*)&Vsl[row * VPITCH + c4]     = l0;
            *(uint32_t*)&Vsl[row * VPITCH + c4 + 2] = l1;
        }
        __syncthreads();

        // --- S = Q K^T (split: Ql*Kh + Qh*Kl + Qh*Kh) ---
        float sacc[8][4];
#pragma unroll
        for (int nt = 0; nt < 8; nt++) {
#pragma unroll
            for (int i = 0; i < 4; i++) sacc[nt][i] = 0.f;
            const uint32_t offBase = (uint32_t)(nt * 8 * VPITCH * 2) + kPart;
#pragma unroll
            for (int ks = 0; ks < 4; ks++) {
                uint32_t bhf[2], blf[2];
                ldsm_x2(bhf[0], bhf[1], khB + offBase + ks * 32);
                ldsm_x2(blf[0], blf[1], klB + offBase + ks * 32);
                mma16816(sacc[nt], ql[ks], bhf);
                mma16816(sacc[nt], qh[ks], blf);
                mma16816(sacc[nt], qh[ks], bhf);
            }
        }

        // scale + causal mask (diagonal tile only)
#pragma unroll
        for (int nt = 0; nt < 8; nt++)
#pragma unroll
            for (int i = 0; i < 4; i++) sacc[nt][i] *= 0.125f;
        if (kt == qt) {
#pragma unroll
            for (int nt = 0; nt < 8; nt++)
#pragma unroll
                for (int i = 0; i < 4; i++) {
                    int col = nt * 8 + 2 * t + (i & 1);
                    int row = w * 16 + g + 8 * (i >> 1);
                    if (col > row) sacc[nt][i] = -1e30f;
                }
        }

        // --- online softmax (per row r = 0: row g, r = 1: row g+8) ---
#pragma unroll
        for (int r = 0; r < 2; r++) {
            float mx = -1e30f;
#pragma unroll
            for (int nt = 0; nt < 8; nt++) {
                mx = fmaxf(mx, sacc[nt][2 * r]);
                mx = fmaxf(mx, sacc[nt][2 * r + 1]);
            }
            mx = fmaxf(mx, __shfl_xor_sync(0xffffffffu, mx, 1));
            mx = fmaxf(mx, __shfl_xor_sync(0xffffffffu, mx, 2));
            float mnew = fmaxf(mrow[r], mx);
            float corr = __expf(mrow[r] - mnew);
            mrow[r] = mnew;
            float rs = 0.f;
#pragma unroll
            for (int nt = 0; nt < 8; nt++) {
                float p0 = __expf(sacc[nt][2 * r]     - mnew);
                float p1 = __expf(sacc[nt][2 * r + 1] - mnew);
                sacc[nt][2 * r] = p0; sacc[nt][2 * r + 1] = p1;
                rs += p0 + p1;
            }
            rs += __shfl_xor_sync(0xffffffffu, rs, 1);
            rs += __shfl_xor_sync(0xffffffffu, rs, 2);
            lrow[r] = lrow[r] * corr + rs;
#pragma unroll
            for (int nt = 0; nt < 8; nt++) {
                oacc[nt][2 * r]     *= corr;
                oacc[nt][2 * r + 1] *= corr;
            }
        }

        // --- O += P V (split: Ph*Vh + Ph*Vl + Pl*Vh) ---
#pragma unroll
        for (int kc = 0; kc < 4; kc++) {
            uint32_t pah[4], pal[4];
            split2(sacc[2 * kc][0],     sacc[2 * kc][1],     pah[0], pal[0]);
            split2(sacc[2 * kc][2],     sacc[2 * kc][3],     pah[1], pal[1]);
            split2(sacc[2 * kc + 1][0], sacc[2 * kc + 1][1], pah[2], pal[2]);
            split2(sacc[2 * kc + 1][2], sacc[2 * kc + 1][3], pah[3], pal[3]);
            const uint32_t offBase = (uint32_t)(kc * 16 * VPITCH * 2) + vPart;
#pragma unroll
            for (int nt = 0; nt < 8; nt++) {
                uint32_t bhf[2], blf[2];
                ldsm_x2_t(bhf[0], bhf[1], vhB + offBase + nt * 16);
                ldsm_x2_t(blf[0], blf[1], vlB + offBase + nt * 16);
                mma16816(oacc[nt], pah, bhf);
                mma16816(oacc[nt], pah, blf);
                mma16816(oacc[nt], pal, bhf);
            }
        }
    }

    // --- epilogue: O /= l, write to g_O[b][s][h*64 + d] ---
    const int bb = bh >> 4;
    const int h  = bh & 15;
#pragma unroll
    for (int r = 0; r < 2; r++) {
        float inv = 1.f / lrow[r];
        int q = q0 + w * 16 + g + 8 * r;
        float* dst = g_O + ((size_t)(bb * SEQ + q)) * DMOD + h * DK;
#pragma unroll
        for (int nt = 0; nt < 8; nt++) {
            *(float2*)&dst[nt * 8 + 2 * t] =
                make_float2(oacc[nt][2 * r] * inv, oacc[nt][2 * r + 1] * inv);
        }
    }
}

// ---------------------------------------------------------------------------
extern "C" void kernel_launch(void* const* d_in, const int* in_sizes, int n_in,
                              void* d_out, int out_size)
{
    const float* X  = (const float*)d_in[0];
    const float* Wq = (const float*)d_in[1];
    const float* Wk = (const float*)d_in[2];
    const float* Wv = (const float*)d_in[3];
    const float* Wo = (const float*)d_in[4];
    float* out = (float*)d_out;

    dim3 ggrid(DMOD / 64, MROWS / 128);   // (16, 32)
    dim3 gblk(256);

    gemm_mma_kernel<<<ggrid, gblk>>>(X, Wq, nullptr, 0);
    gemm_mma_kernel<<<ggrid, gblk>>>(X, Wk, nullptr, 1);
    gemm_mma_kernel<<<ggrid, gblk>>>(X, Wv, nullptr, 2);

    dim3 agrid(SEQ / 64, BATCH * NH);     // (32, 32)
    attn_mma_kernel<<<agrid, 128>>>();

    gemm_mma_kernel<<<ggrid, gblk>>>(X /*ignored*/, Wo, out, 3);
}